// round 9
// baseline (speedup 1.0000x reference)
#include <cuda_runtime.h>
#include <math.h>

// ---------------------------------------------------------------------------
// Problem constants
//   x: [32, 96, 56, 56]  -> GEMMs over K=96, N=32*3136
//   512 window-chunks of 18816 floats each (flat reinterpret views)
// ---------------------------------------------------------------------------
#define NB      32
#define CH96    96
#define SP      3136          // 56*56
#define POSX    224           // spatial tile (14 tiles per batch image)
#define NTILES  14
#define CHUNK   18816         // 24*784 floats per window
#define NWIN    512
#define NTOK    784           // 28*28 tokens per window
#define HDC     24            // per-head channels

// scratch (device globals: allocation-free rule)
__device__ float g_val [NB*CH96*SP];
__device__ float g_feat[NB*CH96*SP];
__device__ float g_xh  [NB*CH96*SP];
__device__ float g_pre [NB*CH96*SP];

#define GEMM_SMEM ((96*96 + 96*POSX) * 4)          // 122880 B

// ---------------------------------------------------------------------------
// GEMM: Y[o,p] = sum_k W[o,k] * X[k,p] + b[o]   per (batch, spatial tile)
// blockIdx = (tile, batch, which-weight). 256 threads, thread tile 6 out x 14 pos,
// fp32x2 packed FMA (FFMA2) accumulation.
// ---------------------------------------------------------------------------
__global__ void __launch_bounds__(256, 1)
gemm_kernel(const float* __restrict__ X,
            const float* __restrict__ W0, const float* __restrict__ B0,
            const float* __restrict__ W1, const float* __restrict__ B1,
            const float* __restrict__ W2, const float* __restrict__ B2,
            float* __restrict__ Y0, float* __restrict__ Y1, float* __restrict__ Y2)
{
    extern __shared__ float sm[];
    float* sW = sm;              // [96][96]
    float* sX = sm + 96*96;      // [96][POSX]

    const int tile = blockIdx.x;
    const int bat  = blockIdx.y;
    const int wz   = blockIdx.z;
    const float* W  = (wz == 0) ? W0 : ((wz == 1) ? W1 : W2);
    const float* Bi = (wz == 0) ? B0 : ((wz == 1) ? B1 : B2);
    float*       Y  = (wz == 0) ? Y0 : ((wz == 1) ? Y1 : Y2);

    const float* xb = X + (size_t)bat * (CH96*SP) + tile * POSX;
    const int tid = threadIdx.x;

    // load W (9216 floats) and X tile (96 x 224) into smem
    for (int i = tid; i < 96*96/4; i += 256)
        ((float4*)sW)[i] = ((const float4*)W)[i];
    for (int i = tid; i < 96*(POSX/4); i += 256) {
        int r = i / (POSX/4), c4 = i % (POSX/4);
        *((float4*)(sX + r*POSX) + c4) = *((const float4*)(xb + (size_t)r*SP) + c4);
    }
    __syncthreads();

    const int tx = tid & 15, ty = tid >> 4;
    const int orow = ty * 6;       // 16*6 = 96
    const int pcol = tx * 14;      // 16*14 = 224

    unsigned long long acc[6][7];
    #pragma unroll
    for (int i = 0; i < 6; i++)
        #pragma unroll
        for (int j = 0; j < 7; j++) acc[i][j] = 0ULL;

    #pragma unroll 2
    for (int k = 0; k < 96; k++) {
        unsigned long long bv[7];
        const float* xr = sX + k*POSX + pcol;
        #pragma unroll
        for (int j = 0; j < 7; j++)
            bv[j] = *(const unsigned long long*)(xr + 2*j);
        #pragma unroll
        for (int i = 0; i < 6; i++) {
            float a = sW[(orow + i)*96 + k];
            unsigned long long aa;
            asm("mov.b64 %0, {%1, %1};" : "=l"(aa) : "f"(a));
            #pragma unroll
            for (int j = 0; j < 7; j++)
                asm("fma.rn.f32x2 %0, %1, %2, %0;"
                    : "+l"(acc[i][j]) : "l"(aa), "l"(bv[j]));
        }
    }

    float* yb = Y + (size_t)bat * (CH96*SP) + tile * POSX;
    #pragma unroll
    for (int i = 0; i < 6; i++) {
        float bias = Bi[orow + i];
        float* yr = yb + (size_t)(orow + i) * SP + pcol;
        #pragma unroll
        for (int j = 0; j < 7; j++) {
            float lo, hi;
            asm("mov.b64 {%0, %1}, %2;" : "=f"(lo), "=f"(hi) : "l"(acc[i][j]));
            float2 v; v.x = lo + bias; v.y = hi + bias;
            *(float2*)(yr + 2*j) = v;
        }
    }
}

// ---------------------------------------------------------------------------
// Per-window clustering. One CTA per window chunk (512 CTAs, 256 threads).
// Views of a flat 18816-float chunk:
//   token-major   T[n][ch] = flat[n*24 + ch]   (value, feature, output)
//   channel-major C[c][s]  = flat[c*784 + s]   (xh pooling, xn cosine)
// ---------------------------------------------------------------------------
#define CLUS_FLOATS (CHUNK*2 + 4*NTOK + NTOK + NTOK + 6*96 + 8 + 192)
#define CLUS_SMEM   (CLUS_FLOATS * 4)

__global__ void __launch_bounds__(256, 1)
cluster_kernel(const float* __restrict__ v_g,
               const float* __restrict__ f_g,
               const float* __restrict__ x_g,
               const float* __restrict__ Wc, const float* __restrict__ bc,
               const float* __restrict__ alpha_p, const float* __restrict__ beta_p,
               float* __restrict__ pre_g)
{
    extern __shared__ float sm[];
    float* sxh  = sm;                    // 18816  xh chunk (flat)
    float* sft  = sxh + CHUNK;           // 18816  feature chunk (flat)
    float* ssim = sft + CHUNK;           // 4*784  softmax sim0 [m][n]
    float* swin = ssim + 4*NTOK;         // 784    winning sigmoid value
    int*   swix = (int*)(swin + NTOK);   // 784    winning center index
    float* px   = (float*)(swix + NTOK); // 96     pool(xh)   flat c*4+s
    float* pf   = px  + 96;              // 96     pool(feat) flat c*4+s
    float* c1f  = pf  + 96;              // 96     conv'd centers flat o*4+s
    float* cnf  = c1f + 96;              // 96     new centers flat m*24+ch
    float* cnn  = cnf + 96;              // 96     normalized centers [m][ch]
    float* agg  = cnn + 96;              // 96     aggregated centers [m][ch]
    float* cnt  = agg + 96;              // 4      assignment counts
    float* nrm  = cnt + 4;               // 4
    float* part = nrm + 4;               // 192    warp partials

    const int b   = blockIdx.x;
    const size_t base = (size_t)b * CHUNK;
    const int tid = threadIdx.x;

    // P0: stage xh + feature chunks
    {
        const float4* gx = (const float4*)(x_g + base);
        const float4* gf = (const float4*)(f_g + base);
        for (int i = tid; i < CHUNK/4; i += 256) {
            ((float4*)sxh)[i] = gx[i];
            ((float4*)sft)[i] = gf[i];
        }
    }
    __syncthreads();

    // P1: adaptive 2x2 pools over channel-major [24,28,28] views
    if (tid < 96) {
        int c = tid >> 2, s = tid & 3;
        int r0 = (s >> 1) * 14, q0 = (s & 1) * 14;
        const float* xc = sxh + c*784;
        const float* fc = sft + c*784;
        float ax = 0.f, af = 0.f;
        for (int r = 0; r < 14; r++) {
            int off = (r0 + r)*28 + q0;
            #pragma unroll
            for (int q = 0; q < 14; q++) { ax += xc[off+q]; af += fc[off+q]; }
        }
        px[tid] = ax * (1.0f/196.0f);
        pf[tid] = af * (1.0f/196.0f);
    }
    if (tid < 4) cnt[tid] = 0.f;
    __syncthreads();

    // P2: centers1 = Wc @ pool + bc  (conv over [24,4]), stored flat o*4+s.
    //     Center row m then reads it as flat[m*24+ch].
    if (tid < 96) {
        int o = tid >> 2, s = tid & 3;
        float v = bc[o];
        #pragma unroll
        for (int c = 0; c < 24; c++) v += Wc[o*24 + c] * px[c*4 + s];
        c1f[tid] = v;
    }
    __syncthreads();

    // P3: logits + softmax over centers (axis M) per token; value streamed from gmem
    for (int n = tid; n < NTOK; n += 256) {
        const float4* vp = (const float4*)(v_g + base + n*24);
        float v[24];
        #pragma unroll
        for (int q = 0; q < 6; q++) {
            float4 t = vp[q];
            v[q*4] = t.x; v[q*4+1] = t.y; v[q*4+2] = t.z; v[q*4+3] = t.w;
        }
        float l[4];
        #pragma unroll
        for (int m = 0; m < 4; m++) {
            float s = 0.f;
            #pragma unroll
            for (int ch = 0; ch < 24; ch++) s += c1f[m*24 + ch] * v[ch];
            l[m] = s;
        }
        float mx = fmaxf(fmaxf(l[0], l[1]), fmaxf(l[2], l[3]));
        float e0 = expf(l[0]-mx), e1 = expf(l[1]-mx), e2 = expf(l[2]-mx), e3 = expf(l[3]-mx);
        float inv = 1.0f / (e0 + e1 + e2 + e3);
        ssim[0*NTOK + n] = e0*inv; ssim[1*NTOK + n] = e1*inv;
        ssim[2*NTOK + n] = e2*inv; ssim[3*NTOK + n] = e3*inv;
    }
    __syncthreads();

    // P3b: centersNew[m][ch] = sum_n sim0[m][n]*feat[n][ch]
    // warp (m, half): lane = ch (24 active), conflict-free token-major reads
    {
        int warp = tid >> 5, lane = tid & 31;
        int m = warp >> 1, half = warp & 1;
        float s = 0.f;
        if (lane < 24) {
            int n0 = half * 392;
            const float* sr = ssim + m*NTOK;
            #pragma unroll 4
            for (int n = n0; n < n0 + 392; n++)
                s += sr[n] * sft[n*24 + lane];
            part[warp*24 + lane] = s;
        }
    }
    __syncthreads();
    if (tid < 96) {
        int m = tid / 24, ch = tid % 24;
        cnf[tid] = part[(2*m)*24 + ch] + part[(2*m+1)*24 + ch];
    }
    __syncthreads();

    // P4: cn[m][ch] = cnf_flat[ch*4+m] (transpose of [24,4] view), L2-normalize rows
    if (tid < 4) {
        float s = 0.f;
        #pragma unroll
        for (int ch = 0; ch < 24; ch++) { float t = cnf[ch*4 + tid]; s += t*t; }
        nrm[tid] = fmaxf(sqrtf(s), 1e-12f);
    }
    __syncthreads();
    if (tid < 96) {
        int m = tid / 24, ch = tid % 24;
        cnn[tid] = cnf[ch*4 + m] / nrm[m];
    }
    __syncthreads();

    const float alpha = *alpha_p, beta = *beta_p;

    // P5: per-token cosine sim vs 4 centers, sigmoid, first-max argmax
    for (int n = tid; n < NTOK; n += 256) {
        float xv[24];
        #pragma unroll
        for (int ch = 0; ch < 24; ch++) xv[ch] = sxh[ch*784 + n];
        float s2 = 0.f;
        #pragma unroll
        for (int ch = 0; ch < 24; ch++) s2 += xv[ch]*xv[ch];
        float rn = 1.0f / fmaxf(sqrtf(s2), 1e-12f);
        float best = -1.0f; int bi = 0;
        #pragma unroll
        for (int m = 0; m < 4; m++) {
            float d = 0.f;
            #pragma unroll
            for (int ch = 0; ch < 24; ch++) d += cnn[m*24 + ch] * xv[ch];
            float z = beta + alpha * (d * rn);
            float sv = 1.0f / (1.0f + expf(-z));
            if (sv > best) { best = sv; bi = m; }   // strict > : first max (jnp.argmax)
        }
        swin[n] = best;
        swix[n] = bi;
        atomicAdd(&cnt[bi], 1.0f);
    }
    __syncthreads();

    // P6: agg[m][ch] = (sum_{n: win==m} swin[n]*feat[n][ch] + pool_feat_flat[m*24+ch]) / (cnt[m]+1)
    {
        int warp = tid >> 5, lane = tid & 31;
        int m = warp >> 1, half = warp & 1;
        float s = 0.f;
        if (lane < 24) {
            int n0 = half * 392;
            #pragma unroll 4
            for (int n = n0; n < n0 + 392; n++)
                if (swix[n] == m) s += swin[n] * sft[n*24 + lane];
            part[warp*24 + lane] = s;
        }
    }
    __syncthreads();
    if (tid < 96) {
        int m = tid / 24;
        agg[tid] = (part[(2*m)*24 + (tid%24)] + part[(2*m+1)*24 + (tid%24)] + pf[tid])
                   / (cnt[m] + 1.0f);
    }
    __syncthreads();

    // P7: broadcast centers back to tokens: out[n][ch] = agg[win(n)][ch] * swin[n]
    for (int n = tid; n < NTOK; n += 256) {
        int bi = swix[n]; float w = swin[n];
        const float* ag = agg + bi*24;
        float4* op = (float4*)(pre_g + base + n*24);
        #pragma unroll
        for (int q = 0; q < 6; q++) {
            float4 t;
            t.x = ag[q*4  ] * w; t.y = ag[q*4+1] * w;
            t.z = ag[q*4+2] * w; t.w = ag[q*4+3] * w;
            op[q] = t;
        }
    }
}

// ---------------------------------------------------------------------------
extern "C" void kernel_launch(void* const* d_in, const int* in_sizes, int n_in,
                              void* d_out, int out_size)
{
    const float* x     = (const float*)d_in[0];
    const float* Wv    = (const float*)d_in[1];
    const float* bv    = (const float*)d_in[2];
    const float* Wf    = (const float*)d_in[3];
    const float* bf    = (const float*)d_in[4];
    const float* W1    = (const float*)d_in[5];
    const float* b1    = (const float*)d_in[6];
    const float* Wc    = (const float*)d_in[7];
    const float* bc    = (const float*)d_in[8];
    const float* W2    = (const float*)d_in[9];
    const float* b2    = (const float*)d_in[10];
    const float* alpha = (const float*)d_in[11];
    const float* beta  = (const float*)d_in[12];
    float* out = (float*)d_out;

    float *val_p, *feat_p, *xh_p, *pre_p;
    cudaGetSymbolAddress((void**)&val_p,  g_val);
    cudaGetSymbolAddress((void**)&feat_p, g_feat);
    cudaGetSymbolAddress((void**)&xh_p,   g_xh);
    cudaGetSymbolAddress((void**)&pre_p,  g_pre);

    cudaFuncSetAttribute(gemm_kernel,    cudaFuncAttributeMaxDynamicSharedMemorySize, GEMM_SMEM);
    cudaFuncSetAttribute(cluster_kernel, cudaFuncAttributeMaxDynamicSharedMemorySize, CLUS_SMEM);

    // A: three fused-shape 1x1 convs (value, feature, xh)
    gemm_kernel<<<dim3(NTILES, NB, 3), 256, GEMM_SMEM>>>(
        x, Wv, bv, Wf, bf, W1, b1, val_p, feat_p, xh_p);

    // B: per-window clustering
    cluster_kernel<<<NWIN, 256, CLUS_SMEM>>>(
        val_p, feat_p, xh_p, Wc, bc, alpha, beta, pre_p);

    // C: output 1x1 conv
    gemm_kernel<<<dim3(NTILES, NB, 1), 256, GEMM_SMEM>>>(
        pre_p, W2, b2, W2, b2, W2, b2, out, out, out);
}

// round 10
// speedup vs baseline: 1.0129x; 1.0129x over previous
#include <cuda_runtime.h>
#include <math.h>

// ---------------------------------------------------------------------------
// Problem constants
//   x: [32, 96, 56, 56]  -> GEMMs over K=96, N=32*3136
//   512 window-chunks of 18816 floats each (flat reinterpret views)
// ---------------------------------------------------------------------------
#define NB      32
#define CH96    96
#define SP      3136          // 56*56
#define POSX    224           // spatial tile (14 tiles per batch image)
#define NTILES  14
#define CHUNK   18816         // 24*784 floats per window
#define NWIN    512
#define NTOK    784           // 28*28 tokens per window
#define HDC     24            // per-head channels

// scratch (device globals: allocation-free rule)
__device__ float g_val [NB*CH96*SP];
__device__ float g_feat[NB*CH96*SP];
__device__ float g_xh  [NB*CH96*SP];
__device__ float g_pre [NB*CH96*SP];

#define GEMM_SMEM ((96*96 + 96*POSX) * 4)          // 122880 B

// ---------------------------------------------------------------------------
// GEMM: Y[o,p] = sum_k W[o,k] * X[k,p] + b[o]   per (batch, spatial tile)
// blockIdx = (tile, batch, which-weight). 256 threads, thread tile 6 out x 14 pos,
// fp32x2 packed FMA (FFMA2) accumulation.
// ---------------------------------------------------------------------------
__global__ void __launch_bounds__(256, 1)
gemm_kernel(const float* __restrict__ X,
            const float* __restrict__ W0, const float* __restrict__ B0,
            const float* __restrict__ W1, const float* __restrict__ B1,
            const float* __restrict__ W2, const float* __restrict__ B2,
            float* __restrict__ Y0, float* __restrict__ Y1, float* __restrict__ Y2)
{
    extern __shared__ float sm[];
    float* sW = sm;              // [96][96]
    float* sX = sm + 96*96;      // [96][POSX]

    const int tile = blockIdx.x;
    const int bat  = blockIdx.y;
    const int wz   = blockIdx.z;
    const float* W  = (wz == 0) ? W0 : ((wz == 1) ? W1 : W2);
    const float* Bi = (wz == 0) ? B0 : ((wz == 1) ? B1 : B2);
    float*       Y  = (wz == 0) ? Y0 : ((wz == 1) ? Y1 : Y2);

    const float* xb = X + (size_t)bat * (CH96*SP) + tile * POSX;
    const int tid = threadIdx.x;

    // load W (9216 floats) and X tile (96 x 224) into smem
    for (int i = tid; i < 96*96/4; i += 256)
        ((float4*)sW)[i] = ((const float4*)W)[i];
    for (int i = tid; i < 96*(POSX/4); i += 256) {
        int r = i / (POSX/4), c4 = i % (POSX/4);
        *((float4*)(sX + r*POSX) + c4) = *((const float4*)(xb + (size_t)r*SP) + c4);
    }
    __syncthreads();

    const int tx = tid & 15, ty = tid >> 4;
    const int orow = ty * 6;       // 16*6 = 96
    const int pcol = tx * 14;      // 16*14 = 224

    unsigned long long acc[6][7];
    #pragma unroll
    for (int i = 0; i < 6; i++)
        #pragma unroll
        for (int j = 0; j < 7; j++) acc[i][j] = 0ULL;

    #pragma unroll 2
    for (int k = 0; k < 96; k++) {
        unsigned long long bv[7];
        const float* xr = sX + k*POSX + pcol;
        #pragma unroll
        for (int j = 0; j < 7; j++)
            bv[j] = *(const unsigned long long*)(xr + 2*j);
        #pragma unroll
        for (int i = 0; i < 6; i++) {
            float a = sW[(orow + i)*96 + k];
            unsigned long long aa;
            asm("mov.b64 %0, {%1, %1};" : "=l"(aa) : "f"(a));
            #pragma unroll
            for (int j = 0; j < 7; j++)
                asm("fma.rn.f32x2 %0, %1, %2, %0;"
                    : "+l"(acc[i][j]) : "l"(aa), "l"(bv[j]));
        }
    }

    float* yb = Y + (size_t)bat * (CH96*SP) + tile * POSX;
    #pragma unroll
    for (int i = 0; i < 6; i++) {
        float bias = Bi[orow + i];
        float* yr = yb + (size_t)(orow + i) * SP + pcol;
        #pragma unroll
        for (int j = 0; j < 7; j++) {
            float lo, hi;
            asm("mov.b64 {%0, %1}, %2;" : "=f"(lo), "=f"(hi) : "l"(acc[i][j]));
            float2 v; v.x = lo + bias; v.y = hi + bias;
            *(float2*)(yr + 2*j) = v;
        }
    }
}

// ---------------------------------------------------------------------------
// Per-window clustering. One CTA per window chunk (512 CTAs, 256 threads).
// Views of a flat 18816-float chunk:
//   token-major   T[n][ch] = flat[n*24 + ch]   (value, feature, output)
//   channel-major C[c][s]  = flat[c*784 + s]   (xh pooling, xn cosine)
// ---------------------------------------------------------------------------
#define CLUS_FLOATS (CHUNK*2 + 4*NTOK + NTOK + NTOK + 6*96 + 8 + 192)
#define CLUS_SMEM   (CLUS_FLOATS * 4)

__global__ void __launch_bounds__(256, 1)
cluster_kernel(const float* __restrict__ v_g,
               const float* __restrict__ f_g,
               const float* __restrict__ x_g,
               const float* __restrict__ Wc, const float* __restrict__ bc,
               const float* __restrict__ alpha_p, const float* __restrict__ beta_p,
               float* __restrict__ pre_g)
{
    extern __shared__ float sm[];
    float* sxh  = sm;                    // 18816  xh chunk (flat)
    float* sft  = sxh + CHUNK;           // 18816  feature chunk (flat)
    float* ssim = sft + CHUNK;           // 4*784  softmax sim0 [m][n]
    float* swin = ssim + 4*NTOK;         // 784    winning sigmoid value
    int*   swix = (int*)(swin + NTOK);   // 784    winning center index
    float* px   = (float*)(swix + NTOK); // 96     pool(xh)   flat c*4+s
    float* pf   = px  + 96;              // 96     pool(feat) flat c*4+s
    float* c1f  = pf  + 96;              // 96     conv'd centers flat o*4+s
    float* cnf  = c1f + 96;              // 96     new centers flat m*24+ch
    float* cnn  = cnf + 96;              // 96     normalized centers [m][ch]
    float* agg  = cnn + 96;              // 96     aggregated centers [m][ch]
    float* cnt  = agg + 96;              // 4      assignment counts
    float* nrm  = cnt + 4;               // 4
    float* part = nrm + 4;               // 192    warp partials

    const int b   = blockIdx.x;
    const size_t base = (size_t)b * CHUNK;
    const int tid = threadIdx.x;

    // P0: stage xh + feature chunks
    {
        const float4* gx = (const float4*)(x_g + base);
        const float4* gf = (const float4*)(f_g + base);
        for (int i = tid; i < CHUNK/4; i += 256) {
            ((float4*)sxh)[i] = gx[i];
            ((float4*)sft)[i] = gf[i];
        }
    }
    __syncthreads();

    // P1: adaptive 2x2 pools over channel-major [24,28,28] views
    if (tid < 96) {
        int c = tid >> 2, s = tid & 3;
        int r0 = (s >> 1) * 14, q0 = (s & 1) * 14;
        const float* xc = sxh + c*784;
        const float* fc = sft + c*784;
        float ax = 0.f, af = 0.f;
        for (int r = 0; r < 14; r++) {
            int off = (r0 + r)*28 + q0;
            #pragma unroll
            for (int q = 0; q < 14; q++) { ax += xc[off+q]; af += fc[off+q]; }
        }
        px[tid] = ax * (1.0f/196.0f);
        pf[tid] = af * (1.0f/196.0f);
    }
    if (tid < 4) cnt[tid] = 0.f;
    __syncthreads();

    // P2: centers1 = Wc @ pool + bc  (conv over [24,4]), stored flat o*4+s.
    //     Center row m then reads it as flat[m*24+ch].
    if (tid < 96) {
        int o = tid >> 2, s = tid & 3;
        float v = bc[o];
        #pragma unroll
        for (int c = 0; c < 24; c++) v += Wc[o*24 + c] * px[c*4 + s];
        c1f[tid] = v;
    }
    __syncthreads();

    // P3: logits + softmax over centers (axis M) per token; value streamed from gmem
    for (int n = tid; n < NTOK; n += 256) {
        const float4* vp = (const float4*)(v_g + base + n*24);
        float v[24];
        #pragma unroll
        for (int q = 0; q < 6; q++) {
            float4 t = vp[q];
            v[q*4] = t.x; v[q*4+1] = t.y; v[q*4+2] = t.z; v[q*4+3] = t.w;
        }
        float l[4];
        #pragma unroll
        for (int m = 0; m < 4; m++) {
            float s = 0.f;
            #pragma unroll
            for (int ch = 0; ch < 24; ch++) s += c1f[m*24 + ch] * v[ch];
            l[m] = s;
        }
        float mx = fmaxf(fmaxf(l[0], l[1]), fmaxf(l[2], l[3]));
        float e0 = expf(l[0]-mx), e1 = expf(l[1]-mx), e2 = expf(l[2]-mx), e3 = expf(l[3]-mx);
        float inv = 1.0f / (e0 + e1 + e2 + e3);
        ssim[0*NTOK + n] = e0*inv; ssim[1*NTOK + n] = e1*inv;
        ssim[2*NTOK + n] = e2*inv; ssim[3*NTOK + n] = e3*inv;
    }
    __syncthreads();

    // P3b: centersNew[m][ch] = sum_n sim0[m][n]*feat[n][ch]
    // warp (m, half): lane = ch (24 active), conflict-free token-major reads
    {
        int warp = tid >> 5, lane = tid & 31;
        int m = warp >> 1, half = warp & 1;
        float s = 0.f;
        if (lane < 24) {
            int n0 = half * 392;
            const float* sr = ssim + m*NTOK;
            #pragma unroll 4
            for (int n = n0; n < n0 + 392; n++)
                s += sr[n] * sft[n*24 + lane];
            part[warp*24 + lane] = s;
        }
    }
    __syncthreads();
    if (tid < 96) {
        int m = tid / 24, ch = tid % 24;
        cnf[tid] = part[(2*m)*24 + ch] + part[(2*m+1)*24 + ch];
    }
    __syncthreads();

    // P4: cn[m][ch] = cnf_flat[ch*4+m] (transpose of [24,4] view), L2-normalize rows
    if (tid < 4) {
        float s = 0.f;
        #pragma unroll
        for (int ch = 0; ch < 24; ch++) { float t = cnf[ch*4 + tid]; s += t*t; }
        nrm[tid] = fmaxf(sqrtf(s), 1e-12f);
    }
    __syncthreads();
    if (tid < 96) {
        int m = tid / 24, ch = tid % 24;
        cnn[tid] = cnf[ch*4 + m] / nrm[m];
    }
    __syncthreads();

    const float alpha = *alpha_p, beta = *beta_p;

    // P5: per-token cosine sim vs 4 centers, sigmoid, first-max argmax
    for (int n = tid; n < NTOK; n += 256) {
        float xv[24];
        #pragma unroll
        for (int ch = 0; ch < 24; ch++) xv[ch] = sxh[ch*784 + n];
        float s2 = 0.f;
        #pragma unroll
        for (int ch = 0; ch < 24; ch++) s2 += xv[ch]*xv[ch];
        float rn = 1.0f / fmaxf(sqrtf(s2), 1e-12f);
        float best = -1.0f; int bi = 0;
        #pragma unroll
        for (int m = 0; m < 4; m++) {
            float d = 0.f;
            #pragma unroll
            for (int ch = 0; ch < 24; ch++) d += cnn[m*24 + ch] * xv[ch];
            float z = beta + alpha * (d * rn);
            float sv = 1.0f / (1.0f + expf(-z));
            if (sv > best) { best = sv; bi = m; }   // strict > : first max (jnp.argmax)
        }
        swin[n] = best;
        swix[n] = bi;
        atomicAdd(&cnt[bi], 1.0f);
    }
    __syncthreads();

    // P6: agg[m][ch] = (sum_{n: win==m} swin[n]*feat[n][ch] + pool_feat_flat[m*24+ch]) / (cnt[m]+1)
    {
        int warp = tid >> 5, lane = tid & 31;
        int m = warp >> 1, half = warp & 1;
        float s = 0.f;
        if (lane < 24) {
            int n0 = half * 392;
            #pragma unroll 4
            for (int n = n0; n < n0 + 392; n++)
                if (swix[n] == m) s += swin[n] * sft[n*24 + lane];
            part[warp*24 + lane] = s;
        }
    }
    __syncthreads();
    if (tid < 96) {
        int m = tid / 24;
        agg[tid] = (part[(2*m)*24 + (tid%24)] + part[(2*m+1)*24 + (tid%24)] + pf[tid])
                   / (cnt[m] + 1.0f);
    }
    __syncthreads();

    // P7: broadcast centers back to tokens: out[n][ch] = agg[win(n)][ch] * swin[n]
    for (int n = tid; n < NTOK; n += 256) {
        int bi = swix[n]; float w = swin[n];
        const float* ag = agg + bi*24;
        float4* op = (float4*)(pre_g + base + n*24);
        #pragma unroll
        for (int q = 0; q < 6; q++) {
            float4 t;
            t.x = ag[q*4  ] * w; t.y = ag[q*4+1] * w;
            t.z = ag[q*4+2] * w; t.w = ag[q*4+3] * w;
            op[q] = t;
        }
    }
}

// ---------------------------------------------------------------------------
extern "C" void kernel_launch(void* const* d_in, const int* in_sizes, int n_in,
                              void* d_out, int out_size)
{
    const float* x     = (const float*)d_in[0];
    const float* Wv    = (const float*)d_in[1];
    const float* bv    = (const float*)d_in[2];
    const float* Wf    = (const float*)d_in[3];
    const float* bf    = (const float*)d_in[4];
    const float* W1    = (const float*)d_in[5];
    const float* b1    = (const float*)d_in[6];
    const float* Wc    = (const float*)d_in[7];
    const float* bc    = (const float*)d_in[8];
    const float* W2    = (const float*)d_in[9];
    const float* b2    = (const float*)d_in[10];
    const float* alpha = (const float*)d_in[11];
    const float* beta  = (const float*)d_in[12];
    float* out = (float*)d_out;

    float *val_p, *feat_p, *xh_p, *pre_p;
    cudaGetSymbolAddress((void**)&val_p,  g_val);
    cudaGetSymbolAddress((void**)&feat_p, g_feat);
    cudaGetSymbolAddress((void**)&xh_p,   g_xh);
    cudaGetSymbolAddress((void**)&pre_p,  g_pre);

    cudaFuncSetAttribute(gemm_kernel,    cudaFuncAttributeMaxDynamicSharedMemorySize, GEMM_SMEM);
    cudaFuncSetAttribute(cluster_kernel, cudaFuncAttributeMaxDynamicSharedMemorySize, CLUS_SMEM);

    // A: three fused-shape 1x1 convs (value, feature, xh)
    gemm_kernel<<<dim3(NTILES, NB, 3), 256, GEMM_SMEM>>>(
        x, Wv, bv, Wf, bf, W1, b1, val_p, feat_p, xh_p);

    // B: per-window clustering
    cluster_kernel<<<NWIN, 256, CLUS_SMEM>>>(
        val_p, feat_p, xh_p, Wc, bc, alpha, beta, pre_p);

    // C: output 1x1 conv
    gemm_kernel<<<dim3(NTILES, NB, 1), 256, GEMM_SMEM>>>(
        pre_p, W2, b2, W2, b2, W2, b2, out, out, out);
}

// round 11
// speedup vs baseline: 1.0151x; 1.0022x over previous
#include <cuda_runtime.h>
#include <math.h>

// ---------------------------------------------------------------------------
// Problem constants
//   x: [32, 96, 56, 56]  -> GEMMs over K=96, N=32*3136
//   512 window-chunks of 18816 floats each (flat reinterpret views)
// ---------------------------------------------------------------------------
#define NB      32
#define CH96    96
#define SP      3136          // 56*56
#define POSX    224           // spatial tile (14 tiles per batch image)
#define NTILES  14
#define CHUNK   18816         // 24*784 floats per window
#define NWIN    512
#define NTOK    784           // 28*28 tokens per window
#define HDC     24            // per-head channels

// scratch (device globals: allocation-free rule)
__device__ float g_val [NB*CH96*SP];
__device__ float g_feat[NB*CH96*SP];
__device__ float g_xh  [NB*CH96*SP];
__device__ float g_pre [NB*CH96*SP];

#define GEMM_SMEM ((96*96 + 96*POSX) * 4)          // 122880 B

// ---------------------------------------------------------------------------
// GEMM: Y[o,p] = sum_k W[o,k] * X[k,p] + b[o]   per (batch, spatial tile)
// blockIdx = (tile, batch, which-weight). 256 threads, thread tile 6 out x 14 pos,
// fp32x2 packed FMA (FFMA2) accumulation.
// ---------------------------------------------------------------------------
__global__ void __launch_bounds__(256, 1)
gemm_kernel(const float* __restrict__ X,
            const float* __restrict__ W0, const float* __restrict__ B0,
            const float* __restrict__ W1, const float* __restrict__ B1,
            const float* __restrict__ W2, const float* __restrict__ B2,
            float* __restrict__ Y0, float* __restrict__ Y1, float* __restrict__ Y2)
{
    extern __shared__ float sm[];
    float* sW = sm;              // [96][96]
    float* sX = sm + 96*96;      // [96][POSX]

    const int tile = blockIdx.x;
    const int bat  = blockIdx.y;
    const int wz   = blockIdx.z;
    const float* W  = (wz == 0) ? W0 : ((wz == 1) ? W1 : W2);
    const float* Bi = (wz == 0) ? B0 : ((wz == 1) ? B1 : B2);
    float*       Y  = (wz == 0) ? Y0 : ((wz == 1) ? Y1 : Y2);

    const float* xb = X + (size_t)bat * (CH96*SP) + tile * POSX;
    const int tid = threadIdx.x;

    // load W (9216 floats) and X tile (96 x 224) into smem
    for (int i = tid; i < 96*96/4; i += 256)
        ((float4*)sW)[i] = ((const float4*)W)[i];
    for (int i = tid; i < 96*(POSX/4); i += 256) {
        int r = i / (POSX/4), c4 = i % (POSX/4);
        *((float4*)(sX + r*POSX) + c4) = *((const float4*)(xb + (size_t)r*SP) + c4);
    }
    __syncthreads();

    const int tx = tid & 15, ty = tid >> 4;
    const int orow = ty * 6;       // 16*6 = 96
    const int pcol = tx * 14;      // 16*14 = 224

    unsigned long long acc[6][7];
    #pragma unroll
    for (int i = 0; i < 6; i++)
        #pragma unroll
        for (int j = 0; j < 7; j++) acc[i][j] = 0ULL;

    #pragma unroll 2
    for (int k = 0; k < 96; k++) {
        unsigned long long bv[7];
        const float* xr = sX + k*POSX + pcol;
        #pragma unroll
        for (int j = 0; j < 7; j++)
            bv[j] = *(const unsigned long long*)(xr + 2*j);
        #pragma unroll
        for (int i = 0; i < 6; i++) {
            float a = sW[(orow + i)*96 + k];
            unsigned long long aa;
            asm("mov.b64 %0, {%1, %1};" : "=l"(aa) : "f"(a));
            #pragma unroll
            for (int j = 0; j < 7; j++)
                asm("fma.rn.f32x2 %0, %1, %2, %0;"
                    : "+l"(acc[i][j]) : "l"(aa), "l"(bv[j]));
        }
    }

    float* yb = Y + (size_t)bat * (CH96*SP) + tile * POSX;
    #pragma unroll
    for (int i = 0; i < 6; i++) {
        float bias = Bi[orow + i];
        float* yr = yb + (size_t)(orow + i) * SP + pcol;
        #pragma unroll
        for (int j = 0; j < 7; j++) {
            float lo, hi;
            asm("mov.b64 {%0, %1}, %2;" : "=f"(lo), "=f"(hi) : "l"(acc[i][j]));
            float2 v; v.x = lo + bias; v.y = hi + bias;
            *(float2*)(yr + 2*j) = v;
        }
    }
}

// ---------------------------------------------------------------------------
// Per-window clustering. One CTA per window chunk (512 CTAs, 256 threads).
// Views of a flat 18816-float chunk:
//   token-major   T[n][ch] = flat[n*24 + ch]   (value, feature, output)
//   channel-major C[c][s]  = flat[c*784 + s]   (xh pooling, xn cosine)
// ---------------------------------------------------------------------------
#define CLUS_FLOATS (CHUNK*2 + 4*NTOK + NTOK + NTOK + 6*96 + 8 + 192)
#define CLUS_SMEM   (CLUS_FLOATS * 4)

__global__ void __launch_bounds__(256, 1)
cluster_kernel(const float* __restrict__ v_g,
               const float* __restrict__ f_g,
               const float* __restrict__ x_g,
               const float* __restrict__ Wc, const float* __restrict__ bc,
               const float* __restrict__ alpha_p, const float* __restrict__ beta_p,
               float* __restrict__ pre_g)
{
    extern __shared__ float sm[];
    float* sxh  = sm;                    // 18816  xh chunk (flat)
    float* sft  = sxh + CHUNK;           // 18816  feature chunk (flat)
    float* ssim = sft + CHUNK;           // 4*784  softmax sim0 [m][n]
    float* swin = ssim + 4*NTOK;         // 784    winning sigmoid value
    int*   swix = (int*)(swin + NTOK);   // 784    winning center index
    float* px   = (float*)(swix + NTOK); // 96     pool(xh)   flat c*4+s
    float* pf   = px  + 96;              // 96     pool(feat) flat c*4+s
    float* c1f  = pf  + 96;              // 96     conv'd centers flat o*4+s
    float* cnf  = c1f + 96;              // 96     new centers flat m*24+ch
    float* cnn  = cnf + 96;              // 96     normalized centers [m][ch]
    float* agg  = cnn + 96;              // 96     aggregated centers [m][ch]
    float* cnt  = agg + 96;              // 4      assignment counts
    float* nrm  = cnt + 4;               // 4
    float* part = nrm + 4;               // 192    warp partials

    const int b   = blockIdx.x;
    const size_t base = (size_t)b * CHUNK;
    const int tid = threadIdx.x;

    // P0: stage xh + feature chunks
    {
        const float4* gx = (const float4*)(x_g + base);
        const float4* gf = (const float4*)(f_g + base);
        for (int i = tid; i < CHUNK/4; i += 256) {
            ((float4*)sxh)[i] = gx[i];
            ((float4*)sft)[i] = gf[i];
        }
    }
    __syncthreads();

    // P1: adaptive 2x2 pools over channel-major [24,28,28] views
    if (tid < 96) {
        int c = tid >> 2, s = tid & 3;
        int r0 = (s >> 1) * 14, q0 = (s & 1) * 14;
        const float* xc = sxh + c*784;
        const float* fc = sft + c*784;
        float ax = 0.f, af = 0.f;
        for (int r = 0; r < 14; r++) {
            int off = (r0 + r)*28 + q0;
            #pragma unroll
            for (int q = 0; q < 14; q++) { ax += xc[off+q]; af += fc[off+q]; }
        }
        px[tid] = ax * (1.0f/196.0f);
        pf[tid] = af * (1.0f/196.0f);
    }
    if (tid < 4) cnt[tid] = 0.f;
    __syncthreads();

    // P2: centers1 = Wc @ pool + bc  (conv over [24,4]), stored flat o*4+s.
    //     Center row m then reads it as flat[m*24+ch].
    if (tid < 96) {
        int o = tid >> 2, s = tid & 3;
        float v = bc[o];
        #pragma unroll
        for (int c = 0; c < 24; c++) v += Wc[o*24 + c] * px[c*4 + s];
        c1f[tid] = v;
    }
    __syncthreads();

    // P3: logits + softmax over centers (axis M) per token; value streamed from gmem
    for (int n = tid; n < NTOK; n += 256) {
        const float4* vp = (const float4*)(v_g + base + n*24);
        float v[24];
        #pragma unroll
        for (int q = 0; q < 6; q++) {
            float4 t = vp[q];
            v[q*4] = t.x; v[q*4+1] = t.y; v[q*4+2] = t.z; v[q*4+3] = t.w;
        }
        float l[4];
        #pragma unroll
        for (int m = 0; m < 4; m++) {
            float s = 0.f;
            #pragma unroll
            for (int ch = 0; ch < 24; ch++) s += c1f[m*24 + ch] * v[ch];
            l[m] = s;
        }
        float mx = fmaxf(fmaxf(l[0], l[1]), fmaxf(l[2], l[3]));
        float e0 = expf(l[0]-mx), e1 = expf(l[1]-mx), e2 = expf(l[2]-mx), e3 = expf(l[3]-mx);
        float inv = 1.0f / (e0 + e1 + e2 + e3);
        ssim[0*NTOK + n] = e0*inv; ssim[1*NTOK + n] = e1*inv;
        ssim[2*NTOK + n] = e2*inv; ssim[3*NTOK + n] = e3*inv;
    }
    __syncthreads();

    // P3b: centersNew[m][ch] = sum_n sim0[m][n]*feat[n][ch]
    // warp (m, half): lane = ch (24 active), conflict-free token-major reads
    {
        int warp = tid >> 5, lane = tid & 31;
        int m = warp >> 1, half = warp & 1;
        float s = 0.f;
        if (lane < 24) {
            int n0 = half * 392;
            const float* sr = ssim + m*NTOK;
            #pragma unroll 4
            for (int n = n0; n < n0 + 392; n++)
                s += sr[n] * sft[n*24 + lane];
            part[warp*24 + lane] = s;
        }
    }
    __syncthreads();
    if (tid < 96) {
        int m = tid / 24, ch = tid % 24;
        cnf[tid] = part[(2*m)*24 + ch] + part[(2*m+1)*24 + ch];
    }
    __syncthreads();

    // P4: cn[m][ch] = cnf_flat[ch*4+m] (transpose of [24,4] view), L2-normalize rows
    if (tid < 4) {
        float s = 0.f;
        #pragma unroll
        for (int ch = 0; ch < 24; ch++) { float t = cnf[ch*4 + tid]; s += t*t; }
        nrm[tid] = fmaxf(sqrtf(s), 1e-12f);
    }
    __syncthreads();
    if (tid < 96) {
        int m = tid / 24, ch = tid % 24;
        cnn[tid] = cnf[ch*4 + m] / nrm[m];
    }
    __syncthreads();

    const float alpha = *alpha_p, beta = *beta_p;

    // P5: per-token cosine sim vs 4 centers, sigmoid, first-max argmax
    for (int n = tid; n < NTOK; n += 256) {
        float xv[24];
        #pragma unroll
        for (int ch = 0; ch < 24; ch++) xv[ch] = sxh[ch*784 + n];
        float s2 = 0.f;
        #pragma unroll
        for (int ch = 0; ch < 24; ch++) s2 += xv[ch]*xv[ch];
        float rn = 1.0f / fmaxf(sqrtf(s2), 1e-12f);
        float best = -1.0f; int bi = 0;
        #pragma unroll
        for (int m = 0; m < 4; m++) {
            float d = 0.f;
            #pragma unroll
            for (int ch = 0; ch < 24; ch++) d += cnn[m*24 + ch] * xv[ch];
            float z = beta + alpha * (d * rn);
            float sv = 1.0f / (1.0f + expf(-z));
            if (sv > best) { best = sv; bi = m; }   // strict > : first max (jnp.argmax)
        }
        swin[n] = best;
        swix[n] = bi;
        atomicAdd(&cnt[bi], 1.0f);
    }
    __syncthreads();

    // P6: agg[m][ch] = (sum_{n: win==m} swin[n]*feat[n][ch] + pool_feat_flat[m*24+ch]) / (cnt[m]+1)
    {
        int warp = tid >> 5, lane = tid & 31;
        int m = warp >> 1, half = warp & 1;
        float s = 0.f;
        if (lane < 24) {
            int n0 = half * 392;
            #pragma unroll 4
            for (int n = n0; n < n0 + 392; n++)
                if (swix[n] == m) s += swin[n] * sft[n*24 + lane];
            part[warp*24 + lane] = s;
        }
    }
    __syncthreads();
    if (tid < 96) {
        int m = tid / 24;
        agg[tid] = (part[(2*m)*24 + (tid%24)] + part[(2*m+1)*24 + (tid%24)] + pf[tid])
                   / (cnt[m] + 1.0f);
    }
    __syncthreads();

    // P7: broadcast centers back to tokens: out[n][ch] = agg[win(n)][ch] * swin[n]
    for (int n = tid; n < NTOK; n += 256) {
        int bi = swix[n]; float w = swin[n];
        const float* ag = agg + bi*24;
        float4* op = (float4*)(pre_g + base + n*24);
        #pragma unroll
        for (int q = 0; q < 6; q++) {
            float4 t;
            t.x = ag[q*4  ] * w; t.y = ag[q*4+1] * w;
            t.z = ag[q*4+2] * w; t.w = ag[q*4+3] * w;
            op[q] = t;
        }
    }
}

// ---------------------------------------------------------------------------
extern "C" void kernel_launch(void* const* d_in, const int* in_sizes, int n_in,
                              void* d_out, int out_size)
{
    const float* x     = (const float*)d_in[0];
    const float* Wv    = (const float*)d_in[1];
    const float* bv    = (const float*)d_in[2];
    const float* Wf    = (const float*)d_in[3];
    const float* bf    = (const float*)d_in[4];
    const float* W1    = (const float*)d_in[5];
    const float* b1    = (const float*)d_in[6];
    const float* Wc    = (const float*)d_in[7];
    const float* bc    = (const float*)d_in[8];
    const float* W2    = (const float*)d_in[9];
    const float* b2    = (const float*)d_in[10];
    const float* alpha = (const float*)d_in[11];
    const float* beta  = (const float*)d_in[12];
    float* out = (float*)d_out;

    float *val_p, *feat_p, *xh_p, *pre_p;
    cudaGetSymbolAddress((void**)&val_p,  g_val);
    cudaGetSymbolAddress((void**)&feat_p, g_feat);
    cudaGetSymbolAddress((void**)&xh_p,   g_xh);
    cudaGetSymbolAddress((void**)&pre_p,  g_pre);

    cudaFuncSetAttribute(gemm_kernel,    cudaFuncAttributeMaxDynamicSharedMemorySize, GEMM_SMEM);
    cudaFuncSetAttribute(cluster_kernel, cudaFuncAttributeMaxDynamicSharedMemorySize, CLUS_SMEM);

    // A: three fused-shape 1x1 convs (value, feature, xh)
    gemm_kernel<<<dim3(NTILES, NB, 3), 256, GEMM_SMEM>>>(
        x, Wv, bv, Wf, bf, W1, b1, val_p, feat_p, xh_p);

    // B: per-window clustering
    cluster_kernel<<<NWIN, 256, CLUS_SMEM>>>(
        val_p, feat_p, xh_p, Wc, bc, alpha, beta, pre_p);

    // C: output 1x1 conv
    gemm_kernel<<<dim3(NTILES, NB, 1), 256, GEMM_SMEM>>>(
        pre_p, W2, b2, W2, b2, W2, b2, out, out, out);
}